// round 1
// baseline (speedup 1.0000x reference)
#include <cuda_runtime.h>
#include <cstdint>

// Problem constants
#define S_DIM 10
#define H_DIM 100
#define N_DIM 50
#define A_DIM 2
#define BETA 3.0f
#define MAXA 5.0f

#define TPB 128
#define GRID 296   // 148 SMs * 2 resident blocks

// Shared memory layout (floats):
//   wv2q : 1250 float4  (jp in [0,50), np in [0,25)) = 5000 f
//   wl2q : 2500 float4  (jp in [0,50), n  in [0,50)) = 10000 f
//   wv1  : 1000 f   [k][j] row-major
//   wl1  : 1000 f
//   bv1  : 100 f
//   bl1  : 100 f
//   bv2  : 50 f
//   bl2  : 100 f  ([n][a])
#define SMEM_BYTES (4*(5000 + 10000 + 1000 + 1000 + 100 + 100 + 50 + 100))

__device__ __forceinline__ float2 ffma2(float2 a, float2 b, float2 c) {
    float2 d;
    asm("fma.rn.f32x2 %0, %1, %2, %3;"
        : "=l"(*reinterpret_cast<unsigned long long*>(&d))
        : "l"(*reinterpret_cast<unsigned long long*>(&a)),
          "l"(*reinterpret_cast<unsigned long long*>(&b)),
          "l"(*reinterpret_cast<unsigned long long*>(&c)));
    return d;
}

__device__ __forceinline__ float fast_tanh(float x) {
    // tanh(x) = 1 - 2/(exp(2x)+1); __expf rel err ~1e-7, handles |x| large via inf
    float e = __expf(2.0f * x);
    return 1.0f - __fdividef(2.0f, e + 1.0f);
}

__global__ __launch_bounds__(TPB)
void net_kernel(const float* __restrict__ s,  const float* __restrict__ a,
                const float* __restrict__ wv1, const float* __restrict__ bv1,
                const float* __restrict__ wv2, const float* __restrict__ bv2,
                const float* __restrict__ wl1, const float* __restrict__ bl1,
                const float* __restrict__ wl2, const float* __restrict__ bl2,
                float* __restrict__ out, int nrows)
{
    extern __shared__ float smem[];
    float4* sh_wv2q = (float4*)smem;                 // 1250
    float4* sh_wl2q = sh_wv2q + 1250;                // 2500
    float*  sh_wv1  = (float*)(sh_wl2q + 2500);      // 1000
    float*  sh_wl1  = sh_wv1 + 1000;                 // 1000
    float*  sh_bv1  = sh_wl1 + 1000;                 // 100
    float*  sh_bl1  = sh_bv1 + 100;                  // 100
    float*  sh_bv2  = sh_bl1 + 100;                  // 50
    float*  sh_bl2  = sh_bv2 + 50;                   // 100

    const int tid = threadIdx.x;

    // ---- Stage + pre-swizzle weights into shared ----
    for (int i = tid; i < 1000; i += TPB) { sh_wv1[i] = wv1[i]; sh_wl1[i] = wl1[i]; }
    for (int i = tid; i < 100;  i += TPB) { sh_bv1[i] = bv1[i]; sh_bl1[i] = bl1[i]; sh_bl2[i] = bl2[i]; }
    for (int i = tid; i < 50;   i += TPB) { sh_bv2[i] = bv2[i]; }
    // wv2q[jp*25+np] = (wv2[2jp][2np], wv2[2jp][2np+1], wv2[2jp+1][2np], wv2[2jp+1][2np+1])
    for (int i = tid; i < 1250; i += TPB) {
        int jp = i / 25, np = i % 25;
        const float* p0 = wv2 + 100 * jp + 2 * np;
        float2 q0 = *(const float2*)(p0);
        float2 q1 = *(const float2*)(p0 + 50);
        sh_wv2q[i] = make_float4(q0.x, q0.y, q1.x, q1.y);
    }
    // wl2 layout [n][h][a]: (n,2jp,0..1),(n,2jp+1,0..1) are 4 contiguous, 16B-aligned floats
    for (int i = tid; i < 2500; i += TPB) {
        int jp = i / 50, n = i % 50;
        sh_wl2q[i] = *(const float4*)(wl2 + n * 200 + 4 * jp);
    }
    __syncthreads();

    const int stride = GRID * TPB;
    for (int b = blockIdx.x * TPB + tid; b < nrows; b += stride) {
        // ---- load s row, a row ----
        float sr[S_DIM];
        {
            const float2* sp = (const float2*)(s + (size_t)b * S_DIM);
            #pragma unroll
            for (int k = 0; k < 5; k++) {
                float2 t = sp[k];
                sr[2 * k] = t.x; sr[2 * k + 1] = t.y;
            }
        }
        float2 av = ((const float2*)a)[b];

        // ---- Phase A: value tower -> cv[50] packed as 25 x f32x2 ----
        float2 cv[25];
        #pragma unroll
        for (int i = 0; i < 25; i++) cv[i] = ((const float2*)sh_bv2)[i];

        for (int jp = 0; jp < 50; ++jp) {
            float2 hacc = ((const float2*)sh_bv1)[jp];
            #pragma unroll
            for (int k = 0; k < S_DIM; k++) {
                float2 w = *(const float2*)(sh_wv1 + k * H_DIM + 2 * jp);
                hacc = ffma2(make_float2(sr[k], sr[k]), w, hacc);
            }
            float r0 = fmaxf(hacc.x, 0.0f), r1 = fmaxf(hacc.y, 0.0f);
            float2 h0 = make_float2(r0, r0), h1 = make_float2(r1, r1);
            const float4* wq = sh_wv2q + jp * 25;
            #pragma unroll
            for (int np = 0; np < 25; np++) {
                float4 w4 = wq[np];
                cv[np] = ffma2(h0, make_float2(w4.x, w4.y), cv[np]);
                cv[np] = ffma2(h1, make_float2(w4.z, w4.w), cv[np]);
            }
        }

        // ---- Phase B: location tower -> loc[50][2] packed over A ----
        float2 loc[50];
        #pragma unroll
        for (int n = 0; n < 50; n++) loc[n] = ((const float2*)sh_bl2)[n];

        for (int jp = 0; jp < 50; ++jp) {
            float2 hacc = ((const float2*)sh_bl1)[jp];
            #pragma unroll
            for (int k = 0; k < S_DIM; k++) {
                float2 w = *(const float2*)(sh_wl1 + k * H_DIM + 2 * jp);
                hacc = ffma2(make_float2(sr[k], sr[k]), w, hacc);
            }
            float r0 = fmaxf(hacc.x, 0.0f), r1 = fmaxf(hacc.y, 0.0f);
            float2 h0 = make_float2(r0, r0), h1 = make_float2(r1, r1);
            const float4* wq = sh_wl2q + jp * 50;
            #pragma unroll
            for (int n = 0; n < 50; n++) {
                float4 w4 = wq[n];
                loc[n] = ffma2(h0, make_float2(w4.x, w4.y), loc[n]);
                loc[n] = ffma2(h1, make_float2(w4.z, w4.w), loc[n]);
            }
        }

        // ---- Epilogue: tanh, RBF softmax (no max-sub needed: exponent <= 0),
        //      single-pass weighted sum ----
        float wsum = 0.0f, vsum = 0.0f;
        #pragma unroll
        for (int np = 0; np < 25; np++) {
            {
                float2 L = loc[2 * np];
                float d0 = MAXA * fast_tanh(L.x) - av.x;
                float d1 = MAXA * fast_tanh(L.y) - av.y;
                float dist = sqrtf(d0 * d0 + d1 * d1);
                float e = __expf(-BETA * dist);
                wsum += e;
                vsum += e * cv[np].x;
            }
            {
                float2 L = loc[2 * np + 1];
                float d0 = MAXA * fast_tanh(L.x) - av.x;
                float d1 = MAXA * fast_tanh(L.y) - av.y;
                float dist = sqrtf(d0 * d0 + d1 * d1);
                float e = __expf(-BETA * dist);
                wsum += e;
                vsum += e * cv[np].y;
            }
        }
        out[b] = vsum / wsum;
    }
}

extern "C" void kernel_launch(void* const* d_in, const int* in_sizes, int n_in,
                              void* d_out, int out_size)
{
    const float* s   = (const float*)d_in[0];
    const float* a   = (const float*)d_in[1];
    const float* wv1 = (const float*)d_in[2];
    const float* bv1 = (const float*)d_in[3];
    const float* wv2 = (const float*)d_in[4];
    const float* bv2 = (const float*)d_in[5];
    const float* wl1 = (const float*)d_in[6];
    const float* bl1 = (const float*)d_in[7];
    const float* wl2 = (const float*)d_in[8];
    const float* bl2 = (const float*)d_in[9];
    float* out = (float*)d_out;

    int nrows = in_sizes[0] / S_DIM;

    cudaFuncSetAttribute(net_kernel, cudaFuncAttributeMaxDynamicSharedMemorySize, SMEM_BYTES);
    net_kernel<<<GRID, TPB, SMEM_BYTES>>>(s, a, wv1, bv1, wv2, bv2,
                                          wl1, bl1, wl2, bl2, out, nrows);
}